// round 11
// baseline (speedup 1.0000x reference)
#include <cuda_runtime.h>
#include <cuda_bf16.h>
#include <math.h>
#include <stdint.h>

#define B_   2048
#define A_   256
#define ED_  200
#define RD_  200
#define HD_  400
#define XD_  800
#define AD_  400
#define NR_  500
#define HUGE_ 1e9f

// ---------------- device scratch ----------------
__device__ __nv_bfloat16 g_Ah [B_ * XD_];
__device__ __nv_bfloat16 g_Al [B_ * XD_];
__device__ __nv_bfloat16 g_h1h[B_ * AD_];
__device__ __nv_bfloat16 g_h1l[B_ * AD_];
__device__ float         g_X2 [B_ * AD_];
__device__ __nv_bfloat16 g_X2h[B_ * 200];
__device__ __nv_bfloat16 g_X2l[B_ * 200];
__device__ __nv_bfloat16 g_W1Th[AD_ * XD_];
__device__ __nv_bfloat16 g_W1Tl[AD_ * XD_];
__device__ __nv_bfloat16 g_W2Th[AD_ * AD_];
__device__ __nv_bfloat16 g_W2Tl[AD_ * AD_];
__device__ __nv_bfloat16 g_Rh [NR_ * RD_];
__device__ __nv_bfloat16 g_Rl [NR_ * RD_];
// split-K partials
__device__ float g_pA0[B_ * AD_];
__device__ float g_pA1[B_ * AD_];
__device__ float g_pP0[B_ * NR_];
__device__ float g_pP1[B_ * NR_];

// ---------------- helpers ----------------
__device__ __forceinline__ uint32_t smem_u32(const void* p) {
    uint32_t a;
    asm("{ .reg .u64 t; cvta.to.shared.u64 t, %1; cvt.u32.u64 %0, t; }" : "=r"(a) : "l"(p));
    return a;
}
#define SW128(x) ((x) ^ (((x) >> 3) & 0x70))
__device__ __forceinline__ void ldsm4(uint32_t* r, uint32_t addr) {
    asm volatile("ldmatrix.sync.aligned.m8n8.x4.shared.b16 {%0,%1,%2,%3}, [%4];"
                 : "=r"(r[0]), "=r"(r[1]), "=r"(r[2]), "=r"(r[3]) : "r"(addr));
}
__device__ __forceinline__ void mma16816(float* c, const uint32_t* a,
                                         uint32_t b0, uint32_t b1) {
    asm volatile(
        "mma.sync.aligned.m16n8k16.row.col.f32.bf16.bf16.f32 "
        "{%0,%1,%2,%3}, {%4,%5,%6,%7}, {%8,%9}, {%0,%1,%2,%3};"
        : "+f"(c[0]), "+f"(c[1]), "+f"(c[2]), "+f"(c[3])
        : "r"(a[0]), "r"(a[1]), "r"(a[2]), "r"(a[3]), "r"(b0), "r"(b1));
}
__device__ __forceinline__ void split_bf16(float v, __nv_bfloat16& h, __nv_bfloat16& l) {
    h = __float2bfloat16(v);
    l = __float2bfloat16(v - __bfloat162float(h));
}
__device__ __forceinline__ void cpasync16(uint32_t dst, const void* src, int sz) {
    asm volatile("cp.async.cg.shared.global [%0], [%1], 16, %2;"
                 :: "r"(dst), "l"(src), "r"(sz) : "memory");
}
#define CP_COMMIT() asm volatile("cp.async.commit_group;" ::: "memory")
#define CP_WAIT0()  asm volatile("cp.async.wait_group 0;" ::: "memory")

// ---------------- fused prep (unchanged) ----------------
#define PREP_A_N   B_
#define W1_KT      25
#define W1_NT      13
#define W2_KT      13
#define W2_NT      13
#define PREP_W1_N  (W1_KT * W1_NT)
#define PREP_W2_N  (W2_KT * W2_NT)
#define PREP_R_N   98
#define PREP_TOTAL (PREP_A_N + PREP_W1_N + PREP_W2_N + PREP_R_N)

__global__ void __launch_bounds__(256)
prep_all_kernel(const int* __restrict__ e, const int* __restrict__ q,
                const float* __restrict__ H,
                const float* __restrict__ ent_emb,
                const float* __restrict__ rel_emb,
                const float* __restrict__ W1,
                const float* __restrict__ W2) {
    const int blk = blockIdx.x;
    const int tid = threadIdx.x;

    if (blk < PREP_A_N) {
        const int b = blk;
        const float* ep = ent_emb + (long)e[b] * ED_;
        const float* hp = H + (long)b * HD_;
        const float* qp = rel_emb + (long)q[b] * RD_;
        const int i4 = tid * 4;
        if (i4 < XD_) {
            float4 v;
            if (i4 < ED_)            v = *reinterpret_cast<const float4*>(ep + i4);
            else if (i4 < ED_ + HD_) v = *reinterpret_cast<const float4*>(hp + (i4 - ED_));
            else                     v = *reinterpret_cast<const float4*>(qp + (i4 - ED_ - HD_));
            __nv_bfloat16 h0, l0, h1, l1, h2, l2, h3, l3;
            split_bf16(v.x, h0, l0); split_bf16(v.y, h1, l1);
            split_bf16(v.z, h2, l2); split_bf16(v.w, h3, l3);
            long o2 = ((long)b * XD_ + i4) >> 1;
            reinterpret_cast<__nv_bfloat162*>(g_Ah)[o2]     = __nv_bfloat162(h0, h1);
            reinterpret_cast<__nv_bfloat162*>(g_Ah)[o2 + 1] = __nv_bfloat162(h2, h3);
            reinterpret_cast<__nv_bfloat162*>(g_Al)[o2]     = __nv_bfloat162(l0, l1);
            reinterpret_cast<__nv_bfloat162*>(g_Al)[o2 + 1] = __nv_bfloat162(l2, l3);
        }
        return;
    }

    if (blk < PREP_A_N + PREP_W1_N + PREP_W2_N) {
        __shared__ float tile[32][33];
        const bool is1 = (blk < PREP_A_N + PREP_W1_N);
        const int t = is1 ? (blk - PREP_A_N) : (blk - PREP_A_N - PREP_W1_N);
        const int K = is1 ? XD_ : AD_;
        const int N = AD_;
        const int NT = is1 ? W1_NT : W2_NT;
        const float* W = is1 ? W1 : W2;
        __nv_bfloat16* WTh = is1 ? g_W1Th : g_W2Th;
        __nv_bfloat16* WTl = is1 ? g_W1Tl : g_W2Tl;
        const int kt = t / NT, nt = t % NT;
        const int k0 = kt * 32, n0 = nt * 32;
        const int tx = tid & 31, ty = tid >> 5;

        #pragma unroll
        for (int r = 0; r < 4; r++) {
            int k = k0 + ty + r * 8;
            int n = n0 + tx;
            if (k < K && n < N) tile[ty + r * 8][tx] = W[(long)k * N + n];
        }
        __syncthreads();
        #pragma unroll
        for (int r = 0; r < 4; r++) {
            int n = n0 + ty + r * 8;
            int k = k0 + tx;
            if (k < K && n < N) {
                __nv_bfloat16 h, l;
                split_bf16(tile[tx][ty + r * 8], h, l);
                WTh[(long)n * K + k] = h;
                WTl[(long)n * K + k] = l;
            }
        }
        return;
    }

    {
        const int t = blk - (PREP_A_N + PREP_W1_N + PREP_W2_N);
        const int idx = (t * 256 + tid) * 4;
        if (idx < NR_ * RD_) {
            float4 v = *reinterpret_cast<const float4*>(rel_emb + idx);
            __nv_bfloat16 h0, l0, h1, l1, h2, l2, h3, l3;
            split_bf16(v.x, h0, l0); split_bf16(v.y, h1, l1);
            split_bf16(v.z, h2, l2); split_bf16(v.w, h3, l3);
            long o2 = idx >> 1;
            reinterpret_cast<__nv_bfloat162*>(g_Rh)[o2]     = __nv_bfloat162(h0, h1);
            reinterpret_cast<__nv_bfloat162*>(g_Rh)[o2 + 1] = __nv_bfloat162(h2, h3);
            reinterpret_cast<__nv_bfloat162*>(g_Rl)[o2]     = __nv_bfloat162(l0, l1);
            reinterpret_cast<__nv_bfloat162*>(g_Rl)[o2 + 1] = __nv_bfloat162(l2, l3);
        }
        return;
    }
}

// ---------------- warp-MMA GEMM, split-K across blockIdx.z ----------------
#define BUFSZ 8192
#define OFF_AH 0
#define OFF_AL (2 * BUFSZ)
#define OFF_BH (4 * BUFSZ)
#define OFF_BL (6 * BUFSZ)
#define MMA_SMEM (8 * BUFSZ)    // 65536

template<int MODE>
__global__ void __launch_bounds__(256)
mma_kernel() {
    constexpr int KREAL  = (MODE == 0) ? 800 : (MODE == 1) ? 400 : 200;
    constexpr int NN     = (MODE == 2) ? 500 : 400;
    constexpr int CHUNKS = (KREAL + 63) / 64;          // 13, 7, 4
    constexpr int SPLIT0 = (MODE == 0) ? 7 : (MODE == 1) ? 4 : 2;

    extern __shared__ __align__(16) uint8_t dyn[];
    const uint32_t sb = smem_u32(dyn);

    const int tid  = threadIdx.x;
    const int wid  = tid >> 5;
    const int lane = tid & 31;
    const int bm = blockIdx.y * 64;
    const int bn = blockIdx.x * 64;
    const int z  = blockIdx.z;
    const int tBeg = z ? SPLIT0 : 0;
    const int tEnd = z ? CHUNKS : SPLIT0;

    const __nv_bfloat16* Ah = (MODE == 0) ? g_Ah : (MODE == 1) ? g_h1h : g_X2h;
    const __nv_bfloat16* Al = (MODE == 0) ? g_Al : (MODE == 1) ? g_h1l : g_X2l;
    const __nv_bfloat16* Bh = (MODE == 0) ? g_W1Th : (MODE == 1) ? g_W2Th : g_Rh;
    const __nv_bfloat16* Bl = (MODE == 0) ? g_W1Tl : (MODE == 1) ? g_W2Tl : g_Rl;
    float* Cp = (MODE == 2) ? (z ? g_pP1 : g_pP0) : (z ? g_pA1 : g_pA0);

    const int lrow = tid >> 2;
    const int lseg0 = tid & 3;
    const int nrow = bn + lrow;
    const bool nok = (nrow < NN);

    auto issue = [&](int t, int buf) {
        #pragma unroll
        for (int ss = 0; ss < 2; ss++) {
            const int seg = lseg0 + ss * 4;
            const int kg = t * 64 + seg * 8;
            const bool kok = (kg < KREAL);
            const int kcl = kok ? kg : 0;
            const uint32_t so = (uint32_t)buf * BUFSZ + SW128((uint32_t)(lrow * 128 + seg * 16));
            const long aoff = (long)(bm + lrow) * KREAL + kcl;
            const long boff = (long)(nok ? nrow : 0) * KREAL + kcl;
            const int szA = kok ? 16 : 0;
            const int szB = (kok && nok) ? 16 : 0;
            cpasync16(sb + OFF_AH + so, Ah + aoff, szA);
            cpasync16(sb + OFF_AL + so, Al + aoff, szA);
            cpasync16(sb + OFF_BH + so, Bh + boff, szB);
            cpasync16(sb + OFF_BL + so, Bl + boff, szB);
        }
    };

    const int m0w = (wid >> 1) * 16;
    const int n0w = (wid & 1) * 32;
    const int arow = m0w + (lane & 15);
    const int acolb = (lane >> 4) * 16;

    float c[4][4] = {};

    issue(tBeg, 0);
    CP_COMMIT();

    for (int t = tBeg; t < tEnd; t++) {
        const int cur = (t - tBeg) & 1;
        CP_WAIT0();
        __syncthreads();
        if (t + 1 < tEnd) { issue(t + 1, cur ^ 1); CP_COMMIT(); }

        const uint32_t bAh = sb + OFF_AH + cur * BUFSZ;
        const uint32_t bAl = sb + OFF_AL + cur * BUFSZ;
        const uint32_t bBh = sb + OFF_BH + cur * BUFSZ;
        const uint32_t bBl = sb + OFF_BL + cur * BUFSZ;

        #pragma unroll
        for (int kc = 0; kc < 4; kc++) {
            const uint32_t kb = kc * 32 + acolb;
            uint32_t ah[4], al[4];
            ldsm4(ah, bAh + SW128((uint32_t)(arow * 128) + kb));
            ldsm4(al, bAl + SW128((uint32_t)(arow * 128) + kb));

            #pragma unroll
            for (int np = 0; np < 2; np++) {
                const int brow = n0w + np * 16 + (lane & 15);
                uint32_t bh[4], bl[4];
                ldsm4(bh, bBh + SW128((uint32_t)(brow * 128) + kb));
                ldsm4(bl, bBl + SW128((uint32_t)(brow * 128) + kb));

                float* c0 = c[np * 2 + 0];
                float* c1 = c[np * 2 + 1];
                mma16816(c0, ah, bh[0], bh[2]);
                mma16816(c0, ah, bl[0], bl[2]);
                mma16816(c0, al, bh[0], bh[2]);
                mma16816(c1, ah, bh[1], bh[3]);
                mma16816(c1, ah, bl[1], bl[3]);
                mma16816(c1, al, bh[1], bh[3]);
            }
        }
    }

    // partial fp32 epilogue
    const int r0 = bm + m0w + (lane >> 2);
    const int r1 = r0 + 8;
    #pragma unroll
    for (int q4 = 0; q4 < 4; q4++) {
        int nc = bn + n0w + q4 * 8 + (lane & 3) * 2;
        if (nc >= NN) continue;
        *reinterpret_cast<float2*>(&Cp[(long)r0 * NN + nc]) = make_float2(c[q4][0], c[q4][1]);
        *reinterpret_cast<float2*>(&Cp[(long)r1 * NN + nc]) = make_float2(c[q4][2], c[q4][3]);
    }
}

// ---------------- finalize: p0+p1+bias (+relu / +splits) ----------------
// MODE 0 -> h1 hi/lo ; MODE 1 -> g_X2 + X2 hi/lo
template<int MODE>
__global__ void __launch_bounds__(256)
fin_kernel(const float* __restrict__ bias) {
    const int i4 = (blockIdx.x * 256 + threadIdx.x) * 4;
    if (i4 >= B_ * AD_) return;
    float4 p0 = *reinterpret_cast<const float4*>(g_pA0 + i4);
    float4 p1 = *reinterpret_cast<const float4*>(g_pA1 + i4);
    const int col = i4 % AD_;
    const int row = i4 / AD_;
    float4 bb = *reinterpret_cast<const float4*>(bias + col);
    float v0 = p0.x + p1.x + bb.x;
    float v1 = p0.y + p1.y + bb.y;
    float v2 = p0.z + p1.z + bb.z;
    float v3 = p0.w + p1.w + bb.w;
    if (MODE == 0) {
        v0 = fmaxf(v0, 0.f); v1 = fmaxf(v1, 0.f);
        v2 = fmaxf(v2, 0.f); v3 = fmaxf(v3, 0.f);
        __nv_bfloat16 h0, l0, h1, l1, h2, l2, h3, l3;
        split_bf16(v0, h0, l0); split_bf16(v1, h1, l1);
        split_bf16(v2, h2, l2); split_bf16(v3, h3, l3);
        long o2 = (long)i4 >> 1;
        reinterpret_cast<__nv_bfloat162*>(g_h1h)[o2]     = __nv_bfloat162(h0, h1);
        reinterpret_cast<__nv_bfloat162*>(g_h1h)[o2 + 1] = __nv_bfloat162(h2, h3);
        reinterpret_cast<__nv_bfloat162*>(g_h1l)[o2]     = __nv_bfloat162(l0, l1);
        reinterpret_cast<__nv_bfloat162*>(g_h1l)[o2 + 1] = __nv_bfloat162(l2, l3);
    } else {
        *reinterpret_cast<float4*>(g_X2 + i4) = make_float4(v0, v1, v2, v3);
        if (col < 200) {
            __nv_bfloat16 h0, l0, h1, l1, h2, l2, h3, l3;
            split_bf16(v0, h0, l0); split_bf16(v1, h1, l1);
            split_bf16(v2, h2, l2); split_bf16(v3, h3, l3);
            long o2 = ((long)row * 200 + col) >> 1;
            reinterpret_cast<__nv_bfloat162*>(g_X2h)[o2]     = __nv_bfloat162(h0, h1);
            reinterpret_cast<__nv_bfloat162*>(g_X2h)[o2 + 1] = __nv_bfloat162(h2, h3);
            reinterpret_cast<__nv_bfloat162*>(g_X2l)[o2]     = __nv_bfloat162(l0, l1);
            reinterpret_cast<__nv_bfloat162*>(g_X2l)[o2 + 1] = __nv_bfloat162(l2, l3);
        }
    }
}

// ---------------- score (P = pP0 + pP1 read inline) ----------------
__device__ __forceinline__ float dot4(float4 a, float4 b) {
    return a.x * b.x + a.y * b.y + a.z * b.z + a.w * b.w;
}
__global__ void __launch_bounds__(256, 8)
score_kernel(const int* __restrict__ r_space,
             const int* __restrict__ e_space,
             const int* __restrict__ action_mask,
             const float* __restrict__ ent_emb,
             float* __restrict__ out_dist,
             float* __restrict__ out_ent) {
    const int b = blockIdx.x;
    const int tid = threadIdx.x;
    const int lane = tid & 31;
    const int warp = tid >> 5;
    const int grp = lane >> 3;
    const int gl = lane & 7;
    const unsigned FULL = 0xffffffffu;

    __shared__ float4 x2e[50];
    __shared__ float sc[A_];
    __shared__ float red[8];
    __shared__ unsigned char alist[8][32];

    if (tid < 50)
        x2e[tid] = reinterpret_cast<const float4*>(g_X2 + (long)b * AD_ + 200)[tid];
    sc[tid] = -1e30f;
    __syncthreads();

    const long base = (long)b * A_;
    const int aidx = warp * 32 + lane;
    const int my_r = r_space[base + aidx];
    const int my_e = e_space[base + aidx];
    const int my_m = action_mask[base + aidx];

    unsigned mbits = __ballot_sync(FULL, my_m != 0);
    const int cnt = __popc(mbits);
    if (my_m) alist[warp][__popc(mbits & ((1u << lane) - 1u))] = (unsigned char)lane;
    __syncwarp();

    const float* P0 = g_pP0 + (long)b * NR_;
    const float* P1 = g_pP1 + (long)b * NR_;

    for (int i0 = 0; i0 < cnt; i0 += 4) {
        int i = i0 + grp;
        bool act = (i < cnt);
        int sl = act ? (int)alist[warp][i] : 0;
        int rr = __shfl_sync(FULL, my_r, sl);
        int ee = __shfl_sync(FULL, my_e, sl);

        const float4* ep = reinterpret_cast<const float4*>(ent_emb + (long)ee * ED_);
        float s = 0.f;
        #pragma unroll
        for (int cc = 0; cc < 6; cc++) {
            float4 ev = ep[cc * 8 + gl];
            s += dot4(ev, x2e[cc * 8 + gl]);
        }
        if (gl < 2) {
            float4 ev = ep[48 + gl];
            s += dot4(ev, x2e[48 + gl]);
        }
        s += __shfl_xor_sync(FULL, s, 1);
        s += __shfl_xor_sync(FULL, s, 2);
        s += __shfl_xor_sync(FULL, s, 4);
        if (act && gl == 0) sc[warp * 32 + sl] = s + P0[rr] + P1[rr];
    }
    __syncthreads();

    float v = sc[tid];
    float mx = v;
    #pragma unroll
    for (int o = 16; o; o >>= 1) mx = fmaxf(mx, __shfl_xor_sync(FULL, mx, o));
    if (lane == 0) red[warp] = mx;
    __syncthreads();
    if (warp == 0) {
        float mm = red[lane & 7];
        #pragma unroll
        for (int o = 4; o; o >>= 1) mm = fmaxf(mm, __shfl_xor_sync(FULL, mm, o));
        if (lane == 0) red[0] = mm;
    }
    __syncthreads();
    mx = red[0];
    __syncthreads();

    float ev = expf(v - mx);
    float sm = ev;
    #pragma unroll
    for (int o = 16; o; o >>= 1) sm += __shfl_xor_sync(FULL, sm, o);
    if (lane == 0) red[warp] = sm;
    __syncthreads();
    if (warp == 0) {
        float ss = red[lane & 7];
        #pragma unroll
        for (int o = 4; o; o >>= 1) ss += __shfl_xor_sync(FULL, ss, o);
        if (lane == 0) red[0] = ss;
    }
    __syncthreads();
    float total = red[0];
    __syncthreads();

    float p = ev / total;
    out_dist[base + tid] = p;

    float t = p * logf(fmaxf(p, 1e-20f));
    float es = t;
    #pragma unroll
    for (int o = 16; o; o >>= 1) es += __shfl_xor_sync(FULL, es, o);
    if (lane == 0) red[warp] = es;
    __syncthreads();
    if (warp == 0) {
        float ss = red[lane & 7];
        #pragma unroll
        for (int o = 4; o; o >>= 1) ss += __shfl_xor_sync(FULL, ss, o);
        if (lane == 0) out_ent[b] = -ss;
    }
}

// ---------------- launch ----------------
extern "C" void kernel_launch(void* const* d_in, const int* in_sizes, int n_in,
                              void* d_out, int out_size) {
    const int*   e        = (const int*)  d_in[0];
    const int*   q        = (const int*)  d_in[1];
    const int*   r_space  = (const int*)  d_in[2];
    const int*   e_space  = (const int*)  d_in[3];
    const int*   mask     = (const int*)  d_in[4];
    const float* H        = (const float*)d_in[5];
    const float* ent_emb  = (const float*)d_in[6];
    const float* rel_emb  = (const float*)d_in[7];
    const float* W1       = (const float*)d_in[8];
    const float* b1       = (const float*)d_in[9];
    const float* W2       = (const float*)d_in[10];
    const float* b2       = (const float*)d_in[11];

    float* out_dist = (float*)d_out;
    float* out_ent  = (float*)d_out + (long)B_ * A_;

    cudaFuncSetAttribute(mma_kernel<0>, cudaFuncAttributeMaxDynamicSharedMemorySize, MMA_SMEM);
    cudaFuncSetAttribute(mma_kernel<1>, cudaFuncAttributeMaxDynamicSharedMemorySize, MMA_SMEM);
    cudaFuncSetAttribute(mma_kernel<2>, cudaFuncAttributeMaxDynamicSharedMemorySize, MMA_SMEM);

    prep_all_kernel<<<PREP_TOTAL, 256>>>(e, q, H, ent_emb, rel_emb, W1, W2);

    mma_kernel<0><<<dim3(7, 32, 2), 256, MMA_SMEM>>>();
    fin_kernel<0><<<800, 256>>>(b1);
    mma_kernel<1><<<dim3(7, 32, 2), 256, MMA_SMEM>>>();
    fin_kernel<1><<<800, 256>>>(b2);
    mma_kernel<2><<<dim3(8, 32, 2), 256, MMA_SMEM>>>();

    score_kernel<<<B_, 256>>>(r_space, e_space, mask, ent_emb,
                              out_dist, out_ent);
}

// round 12
// speedup vs baseline: 1.0733x; 1.0733x over previous
#include <cuda_runtime.h>
#include <cuda_bf16.h>
#include <math.h>
#include <stdint.h>

#define B_   2048
#define A_   256
#define ED_  200
#define RD_  200
#define HD_  400
#define XD_  800
#define AD_  400
#define NR_  500
#define HUGE_ 1e9f

// ---------------- device scratch ----------------
__device__ __nv_bfloat16 g_Ah [B_ * XD_];
__device__ __nv_bfloat16 g_Al [B_ * XD_];
__device__ __nv_bfloat16 g_h1h[B_ * AD_];
__device__ __nv_bfloat16 g_h1l[B_ * AD_];
__device__ float         g_X2 [B_ * AD_];
__device__ __nv_bfloat16 g_X2h[B_ * 200];
__device__ __nv_bfloat16 g_X2l[B_ * 200];
__device__ __nv_bfloat16 g_W1Th[AD_ * XD_];
__device__ __nv_bfloat16 g_W1Tl[AD_ * XD_];
__device__ __nv_bfloat16 g_W2Th[AD_ * AD_];
__device__ __nv_bfloat16 g_W2Tl[AD_ * AD_];
__device__ __nv_bfloat16 g_Rh [NR_ * RD_];
__device__ __nv_bfloat16 g_Rl [NR_ * RD_];
__device__ float         g_P  [B_ * NR_];

// ---------------- helpers ----------------
__device__ __forceinline__ uint32_t smem_u32(const void* p) {
    uint32_t a;
    asm("{ .reg .u64 t; cvta.to.shared.u64 t, %1; cvt.u32.u64 %0, t; }" : "=r"(a) : "l"(p));
    return a;
}
#define SW64(x) ((x) ^ (((x) >> 3) & 0x30))
__device__ __forceinline__ void ldsm4(uint32_t* r, uint32_t addr) {
    asm volatile("ldmatrix.sync.aligned.m8n8.x4.shared.b16 {%0,%1,%2,%3}, [%4];"
                 : "=r"(r[0]), "=r"(r[1]), "=r"(r[2]), "=r"(r[3]) : "r"(addr));
}
__device__ __forceinline__ void mma16816(float* c, const uint32_t* a,
                                         uint32_t b0, uint32_t b1) {
    asm volatile(
        "mma.sync.aligned.m16n8k16.row.col.f32.bf16.bf16.f32 "
        "{%0,%1,%2,%3}, {%4,%5,%6,%7}, {%8,%9}, {%0,%1,%2,%3};"
        : "+f"(c[0]), "+f"(c[1]), "+f"(c[2]), "+f"(c[3])
        : "r"(a[0]), "r"(a[1]), "r"(a[2]), "r"(a[3]), "r"(b0), "r"(b1));
}
__device__ __forceinline__ void split_bf16(float v, __nv_bfloat16& h, __nv_bfloat16& l) {
    h = __float2bfloat16(v);
    l = __float2bfloat16(v - __bfloat162float(h));
}
__device__ __forceinline__ void cpasync16(uint32_t dst, const void* src, int sz) {
    asm volatile("cp.async.cg.shared.global [%0], [%1], 16, %2;"
                 :: "r"(dst), "l"(src), "r"(sz) : "memory");
}
#define CP_COMMIT() asm volatile("cp.async.commit_group;" ::: "memory")
#define CP_WAIT0()  asm volatile("cp.async.wait_group 0;" ::: "memory")

// ---------------- fused prep (unchanged) ----------------
#define PREP_A_N   B_
#define W1_KT      25
#define W1_NT      13
#define W2_KT      13
#define W2_NT      13
#define PREP_W1_N  (W1_KT * W1_NT)
#define PREP_W2_N  (W2_KT * W2_NT)
#define PREP_R_N   98
#define PREP_TOTAL (PREP_A_N + PREP_W1_N + PREP_W2_N + PREP_R_N)

__global__ void __launch_bounds__(256)
prep_all_kernel(const int* __restrict__ e, const int* __restrict__ q,
                const float* __restrict__ H,
                const float* __restrict__ ent_emb,
                const float* __restrict__ rel_emb,
                const float* __restrict__ W1,
                const float* __restrict__ W2) {
    const int blk = blockIdx.x;
    const int tid = threadIdx.x;

    if (blk < PREP_A_N) {
        const int b = blk;
        const float* ep = ent_emb + (long)e[b] * ED_;
        const float* hp = H + (long)b * HD_;
        const float* qp = rel_emb + (long)q[b] * RD_;
        const int i4 = tid * 4;
        if (i4 < XD_) {
            float4 v;
            if (i4 < ED_)            v = *reinterpret_cast<const float4*>(ep + i4);
            else if (i4 < ED_ + HD_) v = *reinterpret_cast<const float4*>(hp + (i4 - ED_));
            else                     v = *reinterpret_cast<const float4*>(qp + (i4 - ED_ - HD_));
            __nv_bfloat16 h0, l0, h1, l1, h2, l2, h3, l3;
            split_bf16(v.x, h0, l0); split_bf16(v.y, h1, l1);
            split_bf16(v.z, h2, l2); split_bf16(v.w, h3, l3);
            long o2 = ((long)b * XD_ + i4) >> 1;
            reinterpret_cast<__nv_bfloat162*>(g_Ah)[o2]     = __nv_bfloat162(h0, h1);
            reinterpret_cast<__nv_bfloat162*>(g_Ah)[o2 + 1] = __nv_bfloat162(h2, h3);
            reinterpret_cast<__nv_bfloat162*>(g_Al)[o2]     = __nv_bfloat162(l0, l1);
            reinterpret_cast<__nv_bfloat162*>(g_Al)[o2 + 1] = __nv_bfloat162(l2, l3);
        }
        return;
    }

    if (blk < PREP_A_N + PREP_W1_N + PREP_W2_N) {
        __shared__ float tile[32][33];
        const bool is1 = (blk < PREP_A_N + PREP_W1_N);
        const int t = is1 ? (blk - PREP_A_N) : (blk - PREP_A_N - PREP_W1_N);
        const int K = is1 ? XD_ : AD_;
        const int N = AD_;
        const int NT = is1 ? W1_NT : W2_NT;
        const float* W = is1 ? W1 : W2;
        __nv_bfloat16* WTh = is1 ? g_W1Th : g_W2Th;
        __nv_bfloat16* WTl = is1 ? g_W1Tl : g_W2Tl;
        const int kt = t / NT, nt = t % NT;
        const int k0 = kt * 32, n0 = nt * 32;
        const int tx = tid & 31, ty = tid >> 5;

        #pragma unroll
        for (int r = 0; r < 4; r++) {
            int k = k0 + ty + r * 8;
            int n = n0 + tx;
            if (k < K && n < N) tile[ty + r * 8][tx] = W[(long)k * N + n];
        }
        __syncthreads();
        #pragma unroll
        for (int r = 0; r < 4; r++) {
            int n = n0 + ty + r * 8;
            int k = k0 + tx;
            if (k < K && n < N) {
                __nv_bfloat16 h, l;
                split_bf16(tile[tx][ty + r * 8], h, l);
                WTh[(long)n * K + k] = h;
                WTl[(long)n * K + k] = l;
            }
        }
        return;
    }

    {
        const int t = blk - (PREP_A_N + PREP_W1_N + PREP_W2_N);
        const int idx = (t * 256 + tid) * 4;
        if (idx < NR_ * RD_) {
            float4 v = *reinterpret_cast<const float4*>(rel_emb + idx);
            __nv_bfloat16 h0, l0, h1, l1, h2, l2, h3, l3;
            split_bf16(v.x, h0, l0); split_bf16(v.y, h1, l1);
            split_bf16(v.z, h2, l2); split_bf16(v.w, h3, l3);
            long o2 = idx >> 1;
            reinterpret_cast<__nv_bfloat162*>(g_Rh)[o2]     = __nv_bfloat162(h0, h1);
            reinterpret_cast<__nv_bfloat162*>(g_Rh)[o2 + 1] = __nv_bfloat162(h2, h3);
            reinterpret_cast<__nv_bfloat162*>(g_Rl)[o2]     = __nv_bfloat162(l0, l1);
            reinterpret_cast<__nv_bfloat162*>(g_Rl)[o2 + 1] = __nv_bfloat162(l2, l3);
        }
        return;
    }
}

// ---------------- warp-MMA GEMM: BK=32, SW64 smem (32KB), 1 sync/iter ----------------
#define BUFSZ 4096
#define OFF_AH 0
#define OFF_AL (2 * BUFSZ)
#define OFF_BH (4 * BUFSZ)
#define OFF_BL (6 * BUFSZ)
#define MMA_SMEM (8 * BUFSZ)    // 32768 -> 4 blocks/SM (regs permitting)

template<int MODE>
__global__ void __launch_bounds__(256, 4)
mma_kernel(const float* __restrict__ bias) {
    constexpr int KREAL = (MODE == 0) ? 800 : (MODE == 1) ? 400 : 200;
    constexpr int NN    = (MODE == 2) ? 500 : 400;
    constexpr int NT    = (KREAL + 31) / 32;    // 25, 13, 7

    extern __shared__ __align__(16) uint8_t dyn[];
    const uint32_t sb = smem_u32(dyn);

    const int tid  = threadIdx.x;
    const int wid  = tid >> 5;
    const int lane = tid & 31;
    const int bm = blockIdx.y * 64;
    const int bn = blockIdx.x * 64;

    const __nv_bfloat16* Ah = (MODE == 0) ? g_Ah : (MODE == 1) ? g_h1h : g_X2h;
    const __nv_bfloat16* Al = (MODE == 0) ? g_Al : (MODE == 1) ? g_h1l : g_X2l;
    const __nv_bfloat16* Bh = (MODE == 0) ? g_W1Th : (MODE == 1) ? g_W2Th : g_Rh;
    const __nv_bfloat16* Bl = (MODE == 0) ? g_W1Tl : (MODE == 1) ? g_W2Tl : g_Rl;

    // loader: thread -> (row 0..63, seg 0..3), one 16B cp.async per array
    const int lrow = tid >> 2;
    const int lseg = tid & 3;
    const int nrow = bn + lrow;
    const bool nok = (nrow < NN);

    auto issue = [&](int t, int buf) {
        const int kg = t * 32 + lseg * 8;
        const bool kok = (kg < KREAL);
        const int kcl = kok ? kg : 0;
        const uint32_t so = (uint32_t)buf * BUFSZ + SW64((uint32_t)(lrow * 64 + lseg * 16));
        const long aoff = (long)(bm + lrow) * KREAL + kcl;
        const long boff = (long)(nok ? nrow : 0) * KREAL + kcl;
        const int szA = kok ? 16 : 0;
        const int szB = (kok && nok) ? 16 : 0;
        cpasync16(sb + OFF_AH + so, Ah + aoff, szA);
        cpasync16(sb + OFF_AL + so, Al + aoff, szA);
        cpasync16(sb + OFF_BH + so, Bh + boff, szB);
        cpasync16(sb + OFF_BL + so, Bl + boff, szB);
    };

    const int m0w = (wid >> 1) * 16;
    const int n0w = (wid & 1) * 32;
    const int arow = m0w + (lane & 15);
    const int acolb = (lane >> 4) * 16;

    float c[4][4] = {};

    issue(0, 0);
    CP_COMMIT();

    for (int t = 0; t < NT; t++) {
        const int cur = t & 1;
        CP_WAIT0();
        __syncthreads();
        if (t + 1 < NT) { issue(t + 1, cur ^ 1); CP_COMMIT(); }

        const uint32_t bAh = sb + OFF_AH + cur * BUFSZ;
        const uint32_t bAl = sb + OFF_AL + cur * BUFSZ;
        const uint32_t bBh = sb + OFF_BH + cur * BUFSZ;
        const uint32_t bBl = sb + OFF_BL + cur * BUFSZ;

        #pragma unroll
        for (int kc = 0; kc < 2; kc++) {
            const uint32_t kb = kc * 32 + acolb;
            uint32_t ah[4], al[4];
            ldsm4(ah, bAh + SW64((uint32_t)(arow * 64) + kb));
            ldsm4(al, bAl + SW64((uint32_t)(arow * 64) + kb));

            #pragma unroll
            for (int np = 0; np < 2; np++) {
                const int brow = n0w + np * 16 + (lane & 15);
                uint32_t bh[4], bl[4];
                ldsm4(bh, bBh + SW64((uint32_t)(brow * 64) + kb));
                ldsm4(bl, bBl + SW64((uint32_t)(brow * 64) + kb));

                float* c0 = c[np * 2 + 0];
                float* c1 = c[np * 2 + 1];
                mma16816(c0, ah, bh[0], bh[2]);
                mma16816(c0, ah, bl[0], bl[2]);
                mma16816(c0, al, bh[0], bh[2]);
                mma16816(c1, ah, bh[1], bh[3]);
                mma16816(c1, ah, bl[1], bl[3]);
                mma16816(c1, al, bh[1], bh[3]);
            }
        }
    }

    // ---------- fused epilogue ----------
    const int m0 = bm + m0w;
    const int n0 = bn + n0w;
    const int r0 = m0 + (lane >> 2);
    const int r1 = r0 + 8;

    #pragma unroll
    for (int q4 = 0; q4 < 4; q4++) {
        int nc = n0 + q4 * 8 + (lane & 3) * 2;
        if (nc >= NN) continue;
        float v00 = c[q4][0], v01 = c[q4][1];
        float v10 = c[q4][2], v11 = c[q4][3];
        if (MODE != 2) {
            float bb0 = bias[nc], bb1 = bias[nc + 1];
            v00 += bb0; v01 += bb1; v10 += bb0; v11 += bb1;
        }
        if (MODE == 0) {
            v00 = fmaxf(v00, 0.f); v01 = fmaxf(v01, 0.f);
            v10 = fmaxf(v10, 0.f); v11 = fmaxf(v11, 0.f);
            __nv_bfloat16 h0, l0, h1, l1;
            split_bf16(v00, h0, l0); split_bf16(v01, h1, l1);
            *reinterpret_cast<__nv_bfloat162*>(&g_h1h[(long)r0 * AD_ + nc]) = __nv_bfloat162(h0, h1);
            *reinterpret_cast<__nv_bfloat162*>(&g_h1l[(long)r0 * AD_ + nc]) = __nv_bfloat162(l0, l1);
            split_bf16(v10, h0, l0); split_bf16(v11, h1, l1);
            *reinterpret_cast<__nv_bfloat162*>(&g_h1h[(long)r1 * AD_ + nc]) = __nv_bfloat162(h0, h1);
            *reinterpret_cast<__nv_bfloat162*>(&g_h1l[(long)r1 * AD_ + nc]) = __nv_bfloat162(l0, l1);
        } else if (MODE == 1) {
            *reinterpret_cast<float2*>(&g_X2[(long)r0 * AD_ + nc]) = make_float2(v00, v01);
            *reinterpret_cast<float2*>(&g_X2[(long)r1 * AD_ + nc]) = make_float2(v10, v11);
            if (nc < 200) {
                __nv_bfloat16 h0, l0, h1, l1;
                split_bf16(v00, h0, l0); split_bf16(v01, h1, l1);
                *reinterpret_cast<__nv_bfloat162*>(&g_X2h[(long)r0 * 200 + nc]) = __nv_bfloat162(h0, h1);
                *reinterpret_cast<__nv_bfloat162*>(&g_X2l[(long)r0 * 200 + nc]) = __nv_bfloat162(l0, l1);
                split_bf16(v10, h0, l0); split_bf16(v11, h1, l1);
                *reinterpret_cast<__nv_bfloat162*>(&g_X2h[(long)r1 * 200 + nc]) = __nv_bfloat162(h0, h1);
                *reinterpret_cast<__nv_bfloat162*>(&g_X2l[(long)r1 * 200 + nc]) = __nv_bfloat162(l0, l1);
            }
        } else {
            *reinterpret_cast<float2*>(&g_P[(long)r0 * NR_ + nc]) = make_float2(v00, v01);
            *reinterpret_cast<float2*>(&g_P[(long)r1 * NR_ + nc]) = make_float2(v10, v11);
        }
    }
}

// ---------------- score (R10 version) ----------------
__device__ __forceinline__ float dot4(float4 a, float4 b) {
    return a.x * b.x + a.y * b.y + a.z * b.z + a.w * b.w;
}
__global__ void __launch_bounds__(256, 8)
score_kernel(const int* __restrict__ r_space,
             const int* __restrict__ e_space,
             const int* __restrict__ action_mask,
             const float* __restrict__ ent_emb,
             float* __restrict__ out_dist,
             float* __restrict__ out_ent) {
    const int b = blockIdx.x;
    const int tid = threadIdx.x;
    const int lane = tid & 31;
    const int warp = tid >> 5;
    const int grp = lane >> 3;
    const int gl = lane & 7;
    const unsigned FULL = 0xffffffffu;

    __shared__ float4 x2e[50];
    __shared__ float sc[A_];
    __shared__ float red[8];
    __shared__ unsigned char alist[8][32];

    if (tid < 50)
        x2e[tid] = reinterpret_cast<const float4*>(g_X2 + (long)b * AD_ + 200)[tid];
    sc[tid] = -1e30f;
    __syncthreads();

    const long base = (long)b * A_;
    const int aidx = warp * 32 + lane;
    const int my_r = r_space[base + aidx];
    const int my_e = e_space[base + aidx];
    const int my_m = action_mask[base + aidx];

    unsigned mbits = __ballot_sync(FULL, my_m != 0);
    const int cnt = __popc(mbits);
    if (my_m) alist[warp][__popc(mbits & ((1u << lane) - 1u))] = (unsigned char)lane;
    __syncwarp();

    const float* Prow = g_P + (long)b * NR_;

    for (int i0 = 0; i0 < cnt; i0 += 4) {
        int i = i0 + grp;
        bool act = (i < cnt);
        int sl = act ? (int)alist[warp][i] : 0;
        int rr = __shfl_sync(FULL, my_r, sl);
        int ee = __shfl_sync(FULL, my_e, sl);

        const float4* ep = reinterpret_cast<const float4*>(ent_emb + (long)ee * ED_);
        float s = 0.f;
        #pragma unroll
        for (int cc = 0; cc < 6; cc++) {
            float4 ev = ep[cc * 8 + gl];
            s += dot4(ev, x2e[cc * 8 + gl]);
        }
        if (gl < 2) {
            float4 ev = ep[48 + gl];
            s += dot4(ev, x2e[48 + gl]);
        }
        s += __shfl_xor_sync(FULL, s, 1);
        s += __shfl_xor_sync(FULL, s, 2);
        s += __shfl_xor_sync(FULL, s, 4);
        if (act && gl == 0) sc[warp * 32 + sl] = s + Prow[rr];
    }
    __syncthreads();

    float v = sc[tid];
    float mx = v;
    #pragma unroll
    for (int o = 16; o; o >>= 1) mx = fmaxf(mx, __shfl_xor_sync(FULL, mx, o));
    if (lane == 0) red[warp] = mx;
    __syncthreads();
    if (warp == 0) {
        float mm = red[lane & 7];
        #pragma unroll
        for (int o = 4; o; o >>= 1) mm = fmaxf(mm, __shfl_xor_sync(FULL, mm, o));
        if (lane == 0) red[0] = mm;
    }
    __syncthreads();
    mx = red[0];
    __syncthreads();

    float ev = expf(v - mx);
    float sm = ev;
    #pragma unroll
    for (int o = 16; o; o >>= 1) sm += __shfl_xor_sync(FULL, sm, o);
    if (lane == 0) red[warp] = sm;
    __syncthreads();
    if (warp == 0) {
        float ss = red[lane & 7];
        #pragma unroll
        for (int o = 4; o; o >>= 1) ss += __shfl_xor_sync(FULL, ss, o);
        if (lane == 0) red[0] = ss;
    }
    __syncthreads();
    float total = red[0];
    __syncthreads();

    float p = ev / total;
    out_dist[base + tid] = p;

    float t = p * logf(fmaxf(p, 1e-20f));
    float es = t;
    #pragma unroll
    for (int o = 16; o; o >>= 1) es += __shfl_xor_sync(FULL, es, o);
    if (lane == 0) red[warp] = es;
    __syncthreads();
    if (warp == 0) {
        float ss = red[lane & 7];
        #pragma unroll
        for (int o = 4; o; o >>= 1) ss += __shfl_xor_sync(FULL, ss, o);
        if (lane == 0) out_ent[b] = -ss;
    }
}

// ---------------- launch ----------------
extern "C" void kernel_launch(void* const* d_in, const int* in_sizes, int n_in,
                              void* d_out, int out_size) {
    const int*   e        = (const int*)  d_in[0];
    const int*   q        = (const int*)  d_in[1];
    const int*   r_space  = (const int*)  d_in[2];
    const int*   e_space  = (const int*)  d_in[3];
    const int*   mask     = (const int*)  d_in[4];
    const float* H        = (const float*)d_in[5];
    const float* ent_emb  = (const float*)d_in[6];
    const float* rel_emb  = (const float*)d_in[7];
    const float* W1       = (const float*)d_in[8];
    const float* b1       = (const float*)d_in[9];
    const float* W2       = (const float*)d_in[10];
    const float* b2       = (const float*)d_in[11];

    float* out_dist = (float*)d_out;
    float* out_ent  = (float*)d_out + (long)B_ * A_;

    cudaFuncSetAttribute(mma_kernel<0>, cudaFuncAttributeMaxDynamicSharedMemorySize, MMA_SMEM);
    cudaFuncSetAttribute(mma_kernel<1>, cudaFuncAttributeMaxDynamicSharedMemorySize, MMA_SMEM);
    cudaFuncSetAttribute(mma_kernel<2>, cudaFuncAttributeMaxDynamicSharedMemorySize, MMA_SMEM);

    prep_all_kernel<<<PREP_TOTAL, 256>>>(e, q, H, ent_emb, rel_emb, W1, W2);

    mma_kernel<0><<<dim3(7, 32), 256, MMA_SMEM>>>(b1);
    mma_kernel<1><<<dim3(7, 32), 256, MMA_SMEM>>>(b2);
    mma_kernel<2><<<dim3(8, 32), 256, MMA_SMEM>>>(nullptr);

    score_kernel<<<B_, 256>>>(r_space, e_space, mask, ent_emb,
                              out_dist, out_ent);
}